// round 6
// baseline (speedup 1.0000x reference)
#include <cuda_runtime.h>
#include <cuda_bf16.h>
#include <cstdint>

#define NB 2048   // batch
#define PP 196    // patches
#define DD 768    // patch dim
#define OO 512    // output dim
#define KT 16     // top-k
#define MTOT (NB * KT)   // 32768 gathered rows

// ---------------- device scratch (no allocations allowed) -------------------
__device__ int            g_topk[MTOT];
__device__ float          g_local[NB * OO];
__device__ __nv_bfloat16  g_Ahi[MTOT * DD];        // gathered patches hi
__device__ __nv_bfloat16  g_Alo[MTOT * DD];        // gathered patches lo
__device__ __nv_bfloat16  g_Fhi[NB * 2 * OO];      // fusion input hi
__device__ __nv_bfloat16  g_Flo[NB * 2 * OO];      // fusion input lo
__device__ __nv_bfloat16  g_WpHi[OO * DD];
__device__ __nv_bfloat16  g_WpLo[OO * DD];
__device__ __nv_bfloat16  g_WfHi[OO * 2 * OO];
__device__ __nv_bfloat16  g_WfLo[OO * 2 * OO];

// ---------------- helpers ----------------------------------------------------
__device__ __forceinline__ uint32_t smem_u32(const void* p) {
    uint32_t a;
    asm("{ .reg .u64 t; cvta.to.shared.u64 t, %1; cvt.u32.u64 %0, t; }" : "=r"(a) : "l"(p));
    return a;
}
#define CP_ASYNC16(dst, src) \
    asm volatile("cp.async.cg.shared.global [%0], [%1], 16;" :: "r"(dst), "l"(src) : "memory")
#define CP_COMMIT() asm volatile("cp.async.commit_group;" ::: "memory")
#define CP_WAIT2()  asm volatile("cp.async.wait_group 2;" ::: "memory")
#define LDMATRIX_X4(r, addr) \
    asm volatile("ldmatrix.sync.aligned.m8n8.x4.shared.b16 {%0,%1,%2,%3}, [%4];" \
        : "=r"((r)[0]), "=r"((r)[1]), "=r"((r)[2]), "=r"((r)[3]) : "r"(addr))
#define MMA16816(d, a, b0, b1) \
    asm volatile("mma.sync.aligned.m16n8k16.row.col.f32.bf16.bf16.f32 " \
        "{%0,%1,%2,%3}, {%4,%5,%6,%7}, {%8,%9}, {%0,%1,%2,%3};" \
        : "+f"((d)[0]), "+f"((d)[1]), "+f"((d)[2]), "+f"((d)[3]) \
        : "r"((a)[0]), "r"((a)[1]), "r"((a)[2]), "r"((a)[3]), "r"(b0), "r"(b1))

__device__ __forceinline__ void split_pack(float a, float b, uint32_t& hi, uint32_t& lo) {
    __nv_bfloat16 ha = __float2bfloat16_rn(a), hb = __float2bfloat16_rn(b);
    __nv_bfloat16 la = __float2bfloat16_rn(a - __bfloat162float(ha));
    __nv_bfloat16 lb = __float2bfloat16_rn(b - __bfloat162float(hb));
    __nv_bfloat162 h2 = __nv_bfloat162(ha, hb), l2 = __nv_bfloat162(la, lb);
    hi = *(uint32_t*)&h2; lo = *(uint32_t*)&l2;
}

// ---------------------------------------------------------------------------
// Kernel 0: weight decomposition (hi/lo bf16)
// ---------------------------------------------------------------------------
__global__ void decomp_kernel(const float* __restrict__ Wp, const float* __restrict__ Wf) {
    int i = blockIdx.x * 256 + threadIdx.x;
    const int NWP = OO * DD;
    if (i < NWP) {
        float a = Wp[i];
        __nv_bfloat16 h = __float2bfloat16_rn(a);
        g_WpHi[i] = h;
        g_WpLo[i] = __float2bfloat16_rn(a - __bfloat162float(h));
    } else {
        int j = i - NWP;
        if (j < OO * 2 * OO) {
            float a = Wf[j];
            __nv_bfloat16 h = __float2bfloat16_rn(a);
            g_WfHi[j] = h;
            g_WfLo[j] = __float2bfloat16_rn(a - __bfloat162float(h));
        }
    }
}

// ---------------------------------------------------------------------------
// Kernel 1: per-patch squared L2 norms + single-warp register top-16
// ---------------------------------------------------------------------------
__global__ void norm_topk_kernel(const float* __restrict__ pt) {
    int n = blockIdx.x;
    __shared__ float norms[PP];

    const float* base = pt + (size_t)n * PP * DD;
    int warp = threadIdx.x >> 5, lane = threadIdx.x & 31;

    for (int p = warp; p < PP; p += 8) {
        const float4* row = (const float4*)(base + p * DD);
        float s = 0.f;
        #pragma unroll
        for (int j = 0; j < (DD / 4) / 32; j++) {
            float4 q = row[j * 32 + lane];
            s += q.x * q.x + q.y * q.y + q.z * q.z + q.w * q.w;
        }
        #pragma unroll
        for (int o = 16; o; o >>= 1) s += __shfl_xor_sync(0xffffffffu, s, o);
        if (lane == 0) norms[p] = s;
    }
    __syncthreads();

    if (warp == 0) {
        float v[7];
        #pragma unroll
        for (int j = 0; j < 7; j++) {
            int p = lane + 32 * j;
            v[j] = (p < PP) ? norms[p] : -1e30f;
        }
        #pragma unroll 1
        for (int it = 0; it < KT; it++) {
            float mx = v[0]; int mj = 0;
            #pragma unroll
            for (int j = 1; j < 7; j++) if (v[j] > mx) { mx = v[j]; mj = j; }
            float bmx = mx; int bl = lane;
            #pragma unroll
            for (int o = 16; o; o >>= 1) {
                float om = __shfl_xor_sync(0xffffffffu, bmx, o);
                int   ol = __shfl_xor_sync(0xffffffffu, bl, o);
                if (om > bmx || (om == bmx && ol < bl)) { bmx = om; bl = ol; }
            }
            int wmj = __shfl_sync(0xffffffffu, mj, bl);
            if (lane == bl) v[mj] = -1e30f;
            if (lane == 0) g_topk[n * KT + it] = bl + 32 * wmj;
        }
    }
}

// ---------------------------------------------------------------------------
// Kernel 2: gather selected patches, split fp32 -> bf16 hi/lo, dense layout
// ---------------------------------------------------------------------------
__global__ void gather_split_kernel(const float* __restrict__ pt) {
    int m = blockIdx.x * 4 + (threadIdx.x >> 6);
    int t = threadIdx.x & 63;
    int p = g_topk[m];
    const float4* src = (const float4*)(pt + ((size_t)(m >> 4) * PP + p) * DD);
    uint2* dhi = (uint2*)(g_Ahi + (size_t)m * DD);
    uint2* dlo = (uint2*)(g_Alo + (size_t)m * DD);
    #pragma unroll
    for (int j = 0; j < 3; j++) {
        int q = t + j * 64;
        float4 v = src[q];
        uint32_t h0, l0, h1, l1;
        split_pack(v.x, v.y, h0, l0);
        split_pack(v.z, v.w, h1, l1);
        dhi[q] = make_uint2(h0, h1);
        dlo[q] = make_uint2(l0, l1);
    }
}

// ---------------------------------------------------------------------------
// Kernel 3/5: bf16 HMMA GEMM, merged 3-term chunks. BM=128, BN=256, BK=32,
// 16 warps (512 thr), warp tile 32x64, cp.async 3-stage, 80B padded rows.
// ---------------------------------------------------------------------------
#define SM_A   10240                 // 128 rows * 80B
#define SM_B   20480                 // 256 rows * 80B
#define OFF_AHI 0
#define OFF_ALO SM_A
#define OFF_BHI (2 * SM_A)
#define OFF_BLO (2 * SM_A + SM_B)
#define SM_STAGE (2 * SM_A + 2 * SM_B)   // 61440
#define SM_TOTAL (3 * SM_STAGE)          // 184320

template<int NCH, bool MAXEPI>
__global__ void __launch_bounds__(512, 1) gemm_mma(
    const __nv_bfloat16* __restrict__ Ahi, const __nv_bfloat16* __restrict__ Alo,
    const __nv_bfloat16* __restrict__ Bhi, const __nv_bfloat16* __restrict__ Blo,
    int ldk, float* __restrict__ outp)
{
    extern __shared__ char smem[];
    uint32_t sb = smem_u32(smem);
    int tid = threadIdx.x, lane = tid & 31, wid = tid >> 5;
    int bn = blockIdx.x, bm = blockIdx.y;
    int warp_m = wid & 3, warp_n = wid >> 2;   // 4 x 4 warps; warp tile 32 x 64

    // ---- async loader: chunk c into stage buffer b (6 cp.async / thread)
    auto issue = [&](int c, int b) {
        int kt = c * 32;
        uint32_t s0 = sb + b * SM_STAGE;
        {
            int r = tid >> 2, q = tid & 3;
            const char* sh = (const char*)(Ahi + (size_t)(bm * 128 + r) * ldk + kt) + q * 16;
            const char* sl = (const char*)(Alo + (size_t)(bm * 128 + r) * ldk + kt) + q * 16;
            CP_ASYNC16(s0 + OFF_AHI + r * 80 + q * 16, sh);
            CP_ASYNC16(s0 + OFF_ALO + r * 80 + q * 16, sl);
        }
        #pragma unroll
        for (int i = 0; i < 2; i++) {
            int idx = i * 512 + tid, r = idx >> 2, q = idx & 3;
            const char* sh = (const char*)(Bhi + (size_t)(bn * 256 + r) * ldk + kt) + q * 16;
            const char* sl = (const char*)(Blo + (size_t)(bn * 256 + r) * ldk + kt) + q * 16;
            CP_ASYNC16(s0 + OFF_BHI + r * 80 + q * 16, sh);
            CP_ASYNC16(s0 + OFF_BLO + r * 80 + q * 16, sl);
        }
        CP_COMMIT();
    };

    float acc[2][8][4] = {};

    issue(0, 0);
    issue(1, 1);
    issue(2, 2);

    int buf = 0;
    for (int c = 0; c < NCH; c++) {
        CP_WAIT2();
        __syncthreads();
        uint32_t s0 = sb + buf * SM_STAGE;

        #pragma unroll
        for (int ks = 0; ks < 2; ks++) {
            uint32_t ah[2][4], al[2][4], bb[4][4];
            uint32_t arow = warp_m * 32 + (lane & 15);
            uint32_t acol = ((lane >> 4) * 8 + ks * 16) * 2;
            #pragma unroll
            for (int mf = 0; mf < 2; mf++)
                LDMATRIX_X4(ah[mf], s0 + OFF_AHI + (arow + mf * 16) * 80 + acol);
            #pragma unroll
            for (int mf = 0; mf < 2; mf++)
                LDMATRIX_X4(al[mf], s0 + OFF_ALO + (arow + mf * 16) * 80 + acol);
            uint32_t brow = warp_n * 64 + (lane & 7) + ((lane >> 4) & 1) * 8;
            uint32_t bcol = (ks * 16 + ((lane >> 3) & 1) * 8) * 2;
            #pragma unroll
            for (int nb = 0; nb < 4; nb++)
                LDMATRIX_X4(bb[nb], s0 + OFF_BHI + (brow + nb * 16) * 80 + bcol);
            // term1: Ahi*Bhi, term3: Alo*Bhi
            #pragma unroll
            for (int mf = 0; mf < 2; mf++)
                #pragma unroll
                for (int nf = 0; nf < 8; nf++) {
                    MMA16816(acc[mf][nf], ah[mf], bb[nf >> 1][(nf & 1) * 2], bb[nf >> 1][(nf & 1) * 2 + 1]);
                    MMA16816(acc[mf][nf], al[mf], bb[nf >> 1][(nf & 1) * 2], bb[nf >> 1][(nf & 1) * 2 + 1]);
                }
            // reload b frags with Blo; term2: Ahi*Blo
            #pragma unroll
            for (int nb = 0; nb < 4; nb++)
                LDMATRIX_X4(bb[nb], s0 + OFF_BLO + (brow + nb * 16) * 80 + bcol);
            #pragma unroll
            for (int mf = 0; mf < 2; mf++)
                #pragma unroll
                for (int nf = 0; nf < 8; nf++)
                    MMA16816(acc[mf][nf], ah[mf], bb[nf >> 1][(nf & 1) * 2], bb[nf >> 1][(nf & 1) * 2 + 1]);
        }
        __syncthreads();
        if (c + 3 < NCH) issue(c + 3, buf); else CP_COMMIT();
        buf = (buf == 2) ? 0 : buf + 1;
    }

    if (MAXEPI) {
        // each warp's 32 rows = 2 full 16-row batch groups
        #pragma unroll
        for (int mf = 0; mf < 2; mf++) {
            int nrow = bm * 8 + warp_m * 2 + mf;      // batch index
            #pragma unroll
            for (int nf = 0; nf < 8; nf++) {
                float m0 = fmaxf(acc[mf][nf][0], acc[mf][nf][2]);
                float m1 = fmaxf(acc[mf][nf][1], acc[mf][nf][3]);
                #pragma unroll
                for (int o = 4; o < 32; o <<= 1) {
                    m0 = fmaxf(m0, __shfl_xor_sync(0xffffffffu, m0, o));
                    m1 = fmaxf(m1, __shfl_xor_sync(0xffffffffu, m1, o));
                }
                if (lane < 4) {
                    int col = bn * 256 + warp_n * 64 + nf * 8 + lane * 2;
                    *(float2*)&outp[(size_t)nrow * OO + col] = make_float2(m0, m1);
                }
            }
        }
    } else {
        #pragma unroll
        for (int mf = 0; mf < 2; mf++) {
            int r0 = bm * 128 + warp_m * 32 + mf * 16 + (lane >> 2);
            #pragma unroll
            for (int nf = 0; nf < 8; nf++) {
                int col = bn * 256 + warp_n * 64 + nf * 8 + (lane & 3) * 2;
                *(float2*)&outp[(size_t)r0 * OO + col] =
                    make_float2(acc[mf][nf][0], acc[mf][nf][1]);
                *(float2*)&outp[(size_t)(r0 + 8) * OO + col] =
                    make_float2(acc[mf][nf][2], acc[mf][nf][3]);
            }
        }
    }
}

// ---------------------------------------------------------------------------
// Kernel 4: build fusion input [cls | g_local] as bf16 hi/lo
// ---------------------------------------------------------------------------
__global__ void fuse_split_kernel(const float* __restrict__ cls) {
    int n = blockIdx.x, t = threadIdx.x;          // 256 threads, 1024 cols
    int c = t * 4;
    const float4* src = (c < OO)
        ? (const float4*)(cls + (size_t)n * OO + c)
        : (const float4*)(g_local + (size_t)n * OO + (c - OO));
    float4 v = *src;
    uint32_t h0, l0, h1, l1;
    split_pack(v.x, v.y, h0, l0);
    split_pack(v.z, v.w, h1, l1);
    ((uint2*)(g_Fhi + (size_t)n * 2 * OO))[t] = make_uint2(h0, h1);
    ((uint2*)(g_Flo + (size_t)n * 2 * OO))[t] = make_uint2(l0, l1);
}

// ---------------------------------------------------------------------------
// Kernel 6: row L2 normalize in-place
// ---------------------------------------------------------------------------
__global__ void normalize_kernel(float* __restrict__ out) {
    int n = blockIdx.x;
    float* row = out + (size_t)n * OO;
    __shared__ float red[8];

    int t = threadIdx.x;
    float2 v = ((float2*)row)[t];
    float s = v.x * v.x + v.y * v.y;
    #pragma unroll
    for (int o = 16; o; o >>= 1) s += __shfl_xor_sync(0xffffffffu, s, o);
    if ((t & 31) == 0) red[t >> 5] = s;
    __syncthreads();
    if (t == 0) {
        float tot = 0.f;
        #pragma unroll
        for (int w = 0; w < 8; w++) tot += red[w];
        red[0] = tot;
    }
    __syncthreads();
    float inv = 1.f / fmaxf(sqrtf(red[0]), 1e-12f);
    v.x *= inv; v.y *= inv;
    ((float2*)row)[t] = v;
}

// ---------------------------------------------------------------------------
extern "C" void kernel_launch(void* const* d_in, const int* in_sizes, int n_in,
                              void* d_out, int out_size) {
    const float* cls = (const float*)d_in[0];   // (2048, 512)
    const float* pt  = (const float*)d_in[1];   // (2048, 196, 768)
    const float* Wp  = (const float*)d_in[2];   // (512, 768)
    const float* Wf  = (const float*)d_in[3];   // (512, 1024)
    float* out = (float*)d_out;                 // (2048, 512)

    __nv_bfloat16 *ahi, *alo, *fhi, *flo, *wph, *wpl, *wfh, *wfl;
    float* loc;
    cudaGetSymbolAddress((void**)&ahi, g_Ahi);
    cudaGetSymbolAddress((void**)&alo, g_Alo);
    cudaGetSymbolAddress((void**)&fhi, g_Fhi);
    cudaGetSymbolAddress((void**)&flo, g_Flo);
    cudaGetSymbolAddress((void**)&wph, g_WpHi);
    cudaGetSymbolAddress((void**)&wpl, g_WpLo);
    cudaGetSymbolAddress((void**)&wfh, g_WfHi);
    cudaGetSymbolAddress((void**)&wfl, g_WfLo);
    cudaGetSymbolAddress((void**)&loc, g_local);

    cudaFuncSetAttribute(gemm_mma<DD / 32, true>,
                         cudaFuncAttributeMaxDynamicSharedMemorySize, SM_TOTAL);
    cudaFuncSetAttribute(gemm_mma<(2 * OO) / 32, false>,
                         cudaFuncAttributeMaxDynamicSharedMemorySize, SM_TOTAL);

    decomp_kernel<<<(OO * DD + OO * 2 * OO + 255) / 256, 256>>>(Wp, Wf);
    norm_topk_kernel<<<NB, 256>>>(pt);
    gather_split_kernel<<<MTOT / 4, 256>>>(pt);
    gemm_mma<DD / 32, true><<<dim3(OO / 256, MTOT / 128), 512, SM_TOTAL>>>(
        ahi, alo, wph, wpl, DD, loc);
    fuse_split_kernel<<<NB, 256>>>(cls);
    gemm_mma<(2 * OO) / 32, false><<<dim3(OO / 256, NB / 128), 512, SM_TOTAL>>>(
        fhi, flo, wfh, wfl, 2 * OO, out);
    normalize_kernel<<<NB, 256>>>(out);
}

// round 7
// speedup vs baseline: 1.6102x; 1.6102x over previous
#include <cuda_runtime.h>
#include <cuda_fp16.h>
#include <cstdint>

#define NB 2048   // batch
#define PP 196    // patches
#define DD 768    // patch dim
#define OO 512    // output dim
#define KT 16     // top-k
#define MTOT (NB * KT)   // 32768 gathered rows

// ---------------- device scratch (no allocations allowed) -------------------
__device__ int    g_topk[MTOT];
__device__ __half g_A[MTOT * DD];        // gathered patches, fp16
__device__ __half g_F[NB * 2 * OO];      // fusion input [cls | local], fp16
__device__ __half g_WpH[OO * DD];
__device__ __half g_WfH[OO * 2 * OO];

// ---------------- helpers ----------------------------------------------------
__device__ __forceinline__ uint32_t smem_u32(const void* p) {
    uint32_t a;
    asm("{ .reg .u64 t; cvta.to.shared.u64 t, %1; cvt.u32.u64 %0, t; }" : "=r"(a) : "l"(p));
    return a;
}
#define CP_ASYNC16(dst, src) \
    asm volatile("cp.async.cg.shared.global [%0], [%1], 16;" :: "r"(dst), "l"(src) : "memory")
#define CP_COMMIT() asm volatile("cp.async.commit_group;" ::: "memory")
#define CP_WAIT2()  asm volatile("cp.async.wait_group 2;" ::: "memory")
#define LDMATRIX_X4(r, addr) \
    asm volatile("ldmatrix.sync.aligned.m8n8.x4.shared.b16 {%0,%1,%2,%3}, [%4];" \
        : "=r"((r)[0]), "=r"((r)[1]), "=r"((r)[2]), "=r"((r)[3]) : "r"(addr))
#define MMA16816(d, a, b0, b1) \
    asm volatile("mma.sync.aligned.m16n8k16.row.col.f32.f16.f16.f32 " \
        "{%0,%1,%2,%3}, {%4,%5,%6,%7}, {%8,%9}, {%0,%1,%2,%3};" \
        : "+f"((d)[0]), "+f"((d)[1]), "+f"((d)[2]), "+f"((d)[3]) \
        : "r"((a)[0]), "r"((a)[1]), "r"((a)[2]), "r"((a)[3]), "r"(b0), "r"(b1))

// ---------------------------------------------------------------------------
// Kernel 0: weight conversion fp32 -> fp16
// ---------------------------------------------------------------------------
__global__ void decomp_kernel(const float* __restrict__ Wp, const float* __restrict__ Wf) {
    int i = blockIdx.x * 256 + threadIdx.x;
    const int NWP = OO * DD;
    if (i < NWP) {
        g_WpH[i] = __float2half_rn(Wp[i]);
    } else {
        int j = i - NWP;
        if (j < OO * 2 * OO) g_WfH[j] = __float2half_rn(Wf[j]);
    }
}

// ---------------------------------------------------------------------------
// Kernel 0b: cls half of fusion input
// ---------------------------------------------------------------------------
__global__ void cls_split_kernel(const float* __restrict__ cls) {
    int n = blockIdx.x, t = threadIdx.x;          // 256 threads, 512 cols
    float2 v = ((const float2*)(cls + (size_t)n * OO))[t];
    ((__half2*)(g_F + (size_t)n * 2 * OO))[t] = __floats2half2_rn(v.x, v.y);
}

// ---------------------------------------------------------------------------
// Kernel 1: per-patch squared L2 norms + single-warp register top-16 +
// fused gather of the 16 selected rows (L2-hot) into dense fp16 g_A.
// ---------------------------------------------------------------------------
__global__ void norm_topk_kernel(const float* __restrict__ pt) {
    int n = blockIdx.x;
    __shared__ float norms[PP];
    __shared__ int   sel[KT];

    const float* base = pt + (size_t)n * PP * DD;
    int warp = threadIdx.x >> 5, lane = threadIdx.x & 31;

    for (int p = warp; p < PP; p += 8) {
        const float4* row = (const float4*)(base + p * DD);
        float s = 0.f;
        #pragma unroll
        for (int j = 0; j < (DD / 4) / 32; j++) {
            float4 q = row[j * 32 + lane];
            s += q.x * q.x + q.y * q.y + q.z * q.z + q.w * q.w;
        }
        #pragma unroll
        for (int o = 16; o; o >>= 1) s += __shfl_xor_sync(0xffffffffu, s, o);
        if (lane == 0) norms[p] = s;
    }
    __syncthreads();

    if (warp == 0) {
        float v[7];
        #pragma unroll
        for (int j = 0; j < 7; j++) {
            int p = lane + 32 * j;
            v[j] = (p < PP) ? norms[p] : -1e30f;
        }
        #pragma unroll 1
        for (int it = 0; it < KT; it++) {
            float mx = v[0]; int mj = 0;
            #pragma unroll
            for (int j = 1; j < 7; j++) if (v[j] > mx) { mx = v[j]; mj = j; }
            float bmx = mx; int bl = lane;
            #pragma unroll
            for (int o = 16; o; o >>= 1) {
                float om = __shfl_xor_sync(0xffffffffu, bmx, o);
                int   ol = __shfl_xor_sync(0xffffffffu, bl, o);
                if (om > bmx || (om == bmx && ol < bl)) { bmx = om; bl = ol; }
            }
            int wmj = __shfl_sync(0xffffffffu, mj, bl);
            if (lane == bl) v[mj] = -1e30f;
            if (lane == 0) {
                int p = bl + 32 * wmj;
                g_topk[n * KT + it] = p;
                sel[it] = p;
            }
        }
    }
    __syncthreads();

    // gather: 8 warps x 2 slots each, rows still L2-resident
    #pragma unroll
    for (int s = 0; s < 2; s++) {
        int slot = warp + s * 8;
        const float4* src = (const float4*)(base + sel[slot] * DD);
        uint2* dst = (uint2*)(g_A + (size_t)(n * KT + slot) * DD);
        #pragma unroll
        for (int j = 0; j < 6; j++) {
            float4 q = src[j * 32 + lane];
            __half2 h0 = __floats2half2_rn(q.x, q.y);
            __half2 h1 = __floats2half2_rn(q.z, q.w);
            dst[j * 32 + lane] = make_uint2(*(uint32_t*)&h0, *(uint32_t*)&h1);
        }
    }
}

// ---------------------------------------------------------------------------
// Kernel 2/3: fp16 HMMA GEMM, single term. BM=128, BN=256, BK=64, 8 warps,
// warp tile 64x64, cp.async 3-stage, 144B padded smem rows (conflict-free).
//   C[m,o] = sum_k A[m,k] * B[o,k]
// MAXEPI: max over 16-row groups -> fp16 into g_F[:, 512:]; else fp32 store.
// ---------------------------------------------------------------------------
#define ROWB  144
#define SM_A  (128 * ROWB)               // 18432
#define SM_B  (256 * ROWB)               // 36864
#define SM_STAGE (SM_A + SM_B)           // 55296
#define SM_TOTAL (3 * SM_STAGE)          // 165888

template<int NCH, bool MAXEPI>
__global__ void __launch_bounds__(256, 1) gemm_mma(
    const __half* __restrict__ A, const __half* __restrict__ B,
    int ldk, void* __restrict__ outp)
{
    extern __shared__ char smem[];
    uint32_t sb = smem_u32(smem);
    int tid = threadIdx.x, lane = tid & 31, wid = tid >> 5;
    int bn = blockIdx.x, bm = blockIdx.y;
    int warp_m = wid & 1, warp_n = wid >> 1;   // 2 x 4 warps; warp tile 64x64

    // ---- async loader: chunk c (64 cols) into stage b. 12 cp.async / thread
    auto issue = [&](int c, int b) {
        int kt = c * 64;
        uint32_t s0 = sb + b * SM_STAGE;
        #pragma unroll
        for (int i = 0; i < 4; i++) {          // A: 128 rows x 8 x 16B
            int idx = i * 256 + tid, r = idx >> 3, q = idx & 7;
            CP_ASYNC16(s0 + r * ROWB + q * 16,
                       (const char*)(A + (size_t)(bm * 128 + r) * ldk + kt) + q * 16);
        }
        #pragma unroll
        for (int i = 0; i < 8; i++) {          // B: 256 rows x 8 x 16B
            int idx = i * 256 + tid, r = idx >> 3, q = idx & 7;
            CP_ASYNC16(s0 + SM_A + r * ROWB + q * 16,
                       (const char*)(B + (size_t)(bn * 256 + r) * ldk + kt) + q * 16);
        }
        CP_COMMIT();
    };

    float acc[4][8][4] = {};

    issue(0, 0);
    issue(1, 1);
    issue(2, 2);

    int buf = 0;
    for (int c = 0; c < NCH; c++) {
        CP_WAIT2();
        __syncthreads();
        uint32_t s0 = sb + buf * SM_STAGE;

        #pragma unroll
        for (int ks = 0; ks < 4; ks++) {
            uint32_t a[4][4], b[4][4];
            uint32_t arow = warp_m * 64 + (lane & 15);
            uint32_t acol = (ks * 16 + (lane >> 4) * 8) * 2;
            #pragma unroll
            for (int mf = 0; mf < 4; mf++)
                LDMATRIX_X4(a[mf], s0 + (arow + mf * 16) * ROWB + acol);
            uint32_t brow = warp_n * 64 + (lane & 7) + ((lane >> 4) & 1) * 8;
            uint32_t bcol = (ks * 16 + ((lane >> 3) & 1) * 8) * 2;
            #pragma unroll
            for (int nb = 0; nb < 4; nb++)
                LDMATRIX_X4(b[nb], s0 + SM_A + (brow + nb * 16) * ROWB + bcol);
            #pragma unroll
            for (int mf = 0; mf < 4; mf++)
                #pragma unroll
                for (int nf = 0; nf < 8; nf++)
                    MMA16816(acc[mf][nf], a[mf], b[nf >> 1][(nf & 1) * 2], b[nf >> 1][(nf & 1) * 2 + 1]);
        }
        __syncthreads();
        if (c + 3 < NCH) issue(c + 3, buf); else CP_COMMIT();
        buf = (buf == 2) ? 0 : buf + 1;
    }

    if (MAXEPI) {
        __half* fout = (__half*)outp;
        #pragma unroll
        for (int mf = 0; mf < 4; mf++) {
            int nrow = bm * 8 + warp_m * 4 + mf;      // batch index
            #pragma unroll
            for (int nf = 0; nf < 8; nf++) {
                float m0 = fmaxf(acc[mf][nf][0], acc[mf][nf][2]);
                float m1 = fmaxf(acc[mf][nf][1], acc[mf][nf][3]);
                #pragma unroll
                for (int o = 4; o < 32; o <<= 1) {
                    m0 = fmaxf(m0, __shfl_xor_sync(0xffffffffu, m0, o));
                    m1 = fmaxf(m1, __shfl_xor_sync(0xffffffffu, m1, o));
                }
                if (lane < 4) {
                    int col = OO + bn * 256 + warp_n * 64 + nf * 8 + lane * 2;
                    __half2 h = __floats2half2_rn(m0, m1);
                    *(__half2*)&fout[(size_t)nrow * (2 * OO) + col] = h;
                }
            }
        }
    } else {
        float* out = (float*)outp;
        #pragma unroll
        for (int mf = 0; mf < 4; mf++) {
            int r0 = bm * 128 + warp_m * 64 + mf * 16 + (lane >> 2);
            #pragma unroll
            for (int nf = 0; nf < 8; nf++) {
                int col = bn * 256 + warp_n * 64 + nf * 8 + (lane & 3) * 2;
                *(float2*)&out[(size_t)r0 * OO + col] =
                    make_float2(acc[mf][nf][0], acc[mf][nf][1]);
                *(float2*)&out[(size_t)(r0 + 8) * OO + col] =
                    make_float2(acc[mf][nf][2], acc[mf][nf][3]);
            }
        }
    }
}

// ---------------------------------------------------------------------------
// Kernel 4: row L2 normalize in-place
// ---------------------------------------------------------------------------
__global__ void normalize_kernel(float* __restrict__ out) {
    int n = blockIdx.x;
    float* row = out + (size_t)n * OO;
    __shared__ float red[8];

    int t = threadIdx.x;
    float2 v = ((float2*)row)[t];
    float s = v.x * v.x + v.y * v.y;
    #pragma unroll
    for (int o = 16; o; o >>= 1) s += __shfl_xor_sync(0xffffffffu, s, o);
    if ((t & 31) == 0) red[t >> 5] = s;
    __syncthreads();
    if (t == 0) {
        float tot = 0.f;
        #pragma unroll
        for (int w = 0; w < 8; w++) tot += red[w];
        red[0] = tot;
    }
    __syncthreads();
    float inv = 1.f / fmaxf(sqrtf(red[0]), 1e-12f);
    v.x *= inv; v.y *= inv;
    ((float2*)row)[t] = v;
}

// ---------------------------------------------------------------------------
extern "C" void kernel_launch(void* const* d_in, const int* in_sizes, int n_in,
                              void* d_out, int out_size) {
    const float* cls = (const float*)d_in[0];   // (2048, 512)
    const float* pt  = (const float*)d_in[1];   // (2048, 196, 768)
    const float* Wp  = (const float*)d_in[2];   // (512, 768)
    const float* Wf  = (const float*)d_in[3];   // (512, 1024)
    float* out = (float*)d_out;                 // (2048, 512)

    __half *a_p, *f_p, *wp_p, *wf_p;
    cudaGetSymbolAddress((void**)&a_p,  g_A);
    cudaGetSymbolAddress((void**)&f_p,  g_F);
    cudaGetSymbolAddress((void**)&wp_p, g_WpH);
    cudaGetSymbolAddress((void**)&wf_p, g_WfH);

    cudaFuncSetAttribute(gemm_mma<DD / 64, true>,
                         cudaFuncAttributeMaxDynamicSharedMemorySize, SM_TOTAL);
    cudaFuncSetAttribute(gemm_mma<(2 * OO) / 64, false>,
                         cudaFuncAttributeMaxDynamicSharedMemorySize, SM_TOTAL);

    decomp_kernel<<<(OO * DD + OO * 2 * OO + 255) / 256, 256>>>(Wp, Wf);
    cls_split_kernel<<<NB, 256>>>(cls);
    norm_topk_kernel<<<NB, 256>>>(pt);
    gemm_mma<DD / 64, true><<<dim3(OO / 256, MTOT / 128), 256, SM_TOTAL>>>(
        a_p, wp_p, DD, f_p);
    gemm_mma<(2 * OO) / 64, false><<<dim3(OO / 256, NB / 128), 256, SM_TOTAL>>>(
        f_p, wf_p, 2 * OO, out);
    normalize_kernel<<<NB, 256>>>(out);
}

// round 8
// speedup vs baseline: 1.6359x; 1.0160x over previous
#include <cuda_runtime.h>
#include <cuda_fp16.h>
#include <cstdint>

#define NB 2048   // batch
#define PP 196    // patches
#define DD 768    // patch dim
#define OO 512    // output dim
#define KT 16     // top-k
#define MTOT (NB * KT)   // 32768 gathered rows

// ---------------- device scratch (no allocations allowed) -------------------
__device__ int    g_topk[MTOT];
__device__ __half g_A[MTOT * DD];        // gathered patches, fp16
__device__ __half g_F[NB * 2 * OO];      // fusion input [cls | local], fp16
__device__ __half g_WpH[OO * DD];
__device__ __half g_WfH[OO * 2 * OO];

// ---------------- helpers ----------------------------------------------------
__device__ __forceinline__ uint32_t smem_u32(const void* p) {
    uint32_t a;
    asm("{ .reg .u64 t; cvta.to.shared.u64 t, %1; cvt.u32.u64 %0, t; }" : "=r"(a) : "l"(p));
    return a;
}
#define CP_ASYNC16(dst, src) \
    asm volatile("cp.async.cg.shared.global [%0], [%1], 16;" :: "r"(dst), "l"(src) : "memory")
#define CP_COMMIT() asm volatile("cp.async.commit_group;" ::: "memory")
#define CP_WAIT2()  asm volatile("cp.async.wait_group 2;" ::: "memory")
#define LDMATRIX_X4(r, addr) \
    asm volatile("ldmatrix.sync.aligned.m8n8.x4.shared.b16 {%0,%1,%2,%3}, [%4];" \
        : "=r"((r)[0]), "=r"((r)[1]), "=r"((r)[2]), "=r"((r)[3]) : "r"(addr))
#define MMA16816(d, a, b0, b1) \
    asm volatile("mma.sync.aligned.m16n8k16.row.col.f32.f16.f16.f32 " \
        "{%0,%1,%2,%3}, {%4,%5,%6,%7}, {%8,%9}, {%0,%1,%2,%3};" \
        : "+f"((d)[0]), "+f"((d)[1]), "+f"((d)[2]), "+f"((d)[3]) \
        : "r"((a)[0]), "r"((a)[1]), "r"((a)[2]), "r"((a)[3]), "r"(b0), "r"(b1))

// ---------------------------------------------------------------------------
// Kernel 0: weight conversion fp32 -> fp16 + cls half of fusion input
// ---------------------------------------------------------------------------
#define NWP (OO * DD)            // 393216
#define NWF (OO * 2 * OO)        // 524288
#define NCLS (NB * OO / 2)       // 524288 float2 pairs
__global__ void prep_kernel(const float* __restrict__ Wp, const float* __restrict__ Wf,
                            const float* __restrict__ cls) {
    int i = blockIdx.x * 256 + threadIdx.x;
    if (i < NWP) {
        g_WpH[i] = __float2half_rn(Wp[i]);
    } else if (i < NWP + NWF) {
        int j = i - NWP;
        g_WfH[j] = __float2half_rn(Wf[j]);
    } else if (i < NWP + NWF + NCLS) {
        int j = i - NWP - NWF;              // float2-pair index into cls
        int n = j >> 8, q = j & 255;        // 256 pairs per row
        float2 v = ((const float2*)cls)[j];
        ((__half2*)(g_F + (size_t)n * 2 * OO))[q] = __floats2half2_rn(v.x, v.y);
    }
}

// ---------------------------------------------------------------------------
// Kernel 1: per-patch squared L2 norms + single-warp register top-16 +
// fused gather of the 16 selected rows (L2-hot) into dense fp16 g_A.
// ---------------------------------------------------------------------------
__global__ void norm_topk_kernel(const float* __restrict__ pt) {
    int n = blockIdx.x;
    __shared__ float norms[PP];
    __shared__ int   sel[KT];

    const float* base = pt + (size_t)n * PP * DD;
    int warp = threadIdx.x >> 5, lane = threadIdx.x & 31;

    for (int p = warp; p < PP; p += 8) {
        const float4* row = (const float4*)(base + p * DD);
        float s = 0.f;
        #pragma unroll
        for (int j = 0; j < (DD / 4) / 32; j++) {
            float4 q = row[j * 32 + lane];
            s += q.x * q.x + q.y * q.y + q.z * q.z + q.w * q.w;
        }
        #pragma unroll
        for (int o = 16; o; o >>= 1) s += __shfl_xor_sync(0xffffffffu, s, o);
        if (lane == 0) norms[p] = s;
    }
    __syncthreads();

    if (warp == 0) {
        float v[7];
        #pragma unroll
        for (int j = 0; j < 7; j++) {
            int p = lane + 32 * j;
            v[j] = (p < PP) ? norms[p] : -1e30f;
        }
        #pragma unroll 1
        for (int it = 0; it < KT; it++) {
            float mx = v[0]; int mj = 0;
            #pragma unroll
            for (int j = 1; j < 7; j++) if (v[j] > mx) { mx = v[j]; mj = j; }
            float bmx = mx; int bl = lane;
            #pragma unroll
            for (int o = 16; o; o >>= 1) {
                float om = __shfl_xor_sync(0xffffffffu, bmx, o);
                int   ol = __shfl_xor_sync(0xffffffffu, bl, o);
                if (om > bmx || (om == bmx && ol < bl)) { bmx = om; bl = ol; }
            }
            int wmj = __shfl_sync(0xffffffffu, mj, bl);
            if (lane == bl) v[mj] = -1e30f;
            if (lane == 0) {
                int p = bl + 32 * wmj;
                g_topk[n * KT + it] = p;
                sel[it] = p;
            }
        }
    }
    __syncthreads();

    // gather: 8 warps x 2 slots each, rows still L2-resident
    #pragma unroll
    for (int s = 0; s < 2; s++) {
        int slot = warp + s * 8;
        const float4* src = (const float4*)(base + sel[slot] * DD);
        uint2* dst = (uint2*)(g_A + (size_t)(n * KT + slot) * DD);
        #pragma unroll
        for (int j = 0; j < 6; j++) {
            float4 q = src[j * 32 + lane];
            __half2 h0 = __floats2half2_rn(q.x, q.y);
            __half2 h1 = __floats2half2_rn(q.z, q.w);
            dst[j * 32 + lane] = make_uint2(*(uint32_t*)&h0, *(uint32_t*)&h1);
        }
    }
}

// ---------------------------------------------------------------------------
// Kernel 2/3: fp16 HMMA GEMM. BM=128, BN=256, BK=64, 8 warps, warp tile
// 64x64, cp.async 4-stage single-sync pipeline, 144B padded rows.
//   C[m,o] = sum_k A[m,k] * B[o,k]
// MAXEPI: max over 16-row groups -> fp16 into g_F[:, 512:]; else fp32 store.
// ---------------------------------------------------------------------------
#define ROWB  144
#define SM_A  (128 * ROWB)               // 18432
#define SM_B  (256 * ROWB)               // 36864
#define SM_STAGE (SM_A + SM_B)           // 55296
#define SM_TOTAL (4 * SM_STAGE)          // 221184

template<int NCH, bool MAXEPI>
__global__ void __launch_bounds__(256, 1) gemm_mma(
    const __half* __restrict__ A, const __half* __restrict__ B,
    int ldk, void* __restrict__ outp)
{
    extern __shared__ char smem[];
    uint32_t sb = smem_u32(smem);
    int tid = threadIdx.x, lane = tid & 31, wid = tid >> 5;
    int bn = blockIdx.x, bm = blockIdx.y;
    int warp_m = wid & 1, warp_n = wid >> 1;   // 2 x 4 warps; warp tile 64x64

    // ---- async loader: chunk c (64 cols) into stage b. 12 cp.async / thread
    auto issue = [&](int c, int b) {
        int kt = c * 64;
        uint32_t s0 = sb + b * SM_STAGE;
        #pragma unroll
        for (int i = 0; i < 4; i++) {          // A: 128 rows x 8 x 16B
            int idx = i * 256 + tid, r = idx >> 3, q = idx & 7;
            CP_ASYNC16(s0 + r * ROWB + q * 16,
                       (const char*)(A + (size_t)(bm * 128 + r) * ldk + kt) + q * 16);
        }
        #pragma unroll
        for (int i = 0; i < 8; i++) {          // B: 256 rows x 8 x 16B
            int idx = i * 256 + tid, r = idx >> 3, q = idx & 7;
            CP_ASYNC16(s0 + SM_A + r * ROWB + q * 16,
                       (const char*)(B + (size_t)(bn * 256 + r) * ldk + kt) + q * 16);
        }
        CP_COMMIT();
    };

    float acc[4][8][4] = {};

    issue(0, 0);
    issue(1, 1);
    issue(2, 2);

    for (int c = 0; c < NCH; c++) {
        // pending<=2 with one commit/iter => chunk c's data complete (this thread)
        CP_WAIT2();
        __syncthreads();   // all threads' chunk-c data visible; buffer (c+3)&3 free
        if (c + 3 < NCH) issue(c + 3, (c + 3) & 3); else CP_COMMIT();

        uint32_t s0 = sb + (c & 3) * SM_STAGE;
        #pragma unroll
        for (int ks = 0; ks < 4; ks++) {
            uint32_t a[4][4], b[4][4];
            uint32_t arow = warp_m * 64 + (lane & 15);
            uint32_t acol = (ks * 16 + (lane >> 4) * 8) * 2;
            #pragma unroll
            for (int mf = 0; mf < 4; mf++)
                LDMATRIX_X4(a[mf], s0 + (arow + mf * 16) * ROWB + acol);
            uint32_t brow = warp_n * 64 + (lane & 7) + ((lane >> 4) & 1) * 8;
            uint32_t bcol = (ks * 16 + ((lane >> 3) & 1) * 8) * 2;
            #pragma unroll
            for (int nb = 0; nb < 4; nb++)
                LDMATRIX_X4(b[nb], s0 + SM_A + (brow + nb * 16) * ROWB + bcol);
            #pragma unroll
            for (int mf = 0; mf < 4; mf++)
                #pragma unroll
                for (int nf = 0; nf < 8; nf++)
                    MMA16816(acc[mf][nf], a[mf], b[nf >> 1][(nf & 1) * 2], b[nf >> 1][(nf & 1) * 2 + 1]);
        }
    }

    if (MAXEPI) {
        __half* fout = (__half*)outp;
        #pragma unroll
        for (int mf = 0; mf < 4; mf++) {
            int nrow = bm * 8 + warp_m * 4 + mf;      // batch index
            #pragma unroll
            for (int nf = 0; nf < 8; nf++) {
                float m0 = fmaxf(acc[mf][nf][0], acc[mf][nf][2]);
                float m1 = fmaxf(acc[mf][nf][1], acc[mf][nf][3]);
                #pragma unroll
                for (int o = 4; o < 32; o <<= 1) {
                    m0 = fmaxf(m0, __shfl_xor_sync(0xffffffffu, m0, o));
                    m1 = fmaxf(m1, __shfl_xor_sync(0xffffffffu, m1, o));
                }
                if (lane < 4) {
                    int col = OO + bn * 256 + warp_n * 64 + nf * 8 + lane * 2;
                    __half2 h = __floats2half2_rn(m0, m1);
                    *(__half2*)&fout[(size_t)nrow * (2 * OO) + col] = h;
                }
            }
        }
    } else {
        float* out = (float*)outp;
        #pragma unroll
        for (int mf = 0; mf < 4; mf++) {
            int r0 = bm * 128 + warp_m * 64 + mf * 16 + (lane >> 2);
            #pragma unroll
            for (int nf = 0; nf < 8; nf++) {
                int col = bn * 256 + warp_n * 64 + nf * 8 + (lane & 3) * 2;
                *(float2*)&out[(size_t)r0 * OO + col] =
                    make_float2(acc[mf][nf][0], acc[mf][nf][1]);
                *(float2*)&out[(size_t)(r0 + 8) * OO + col] =
                    make_float2(acc[mf][nf][2], acc[mf][nf][3]);
            }
        }
    }
}

// ---------------------------------------------------------------------------
// Kernel 4: row L2 normalize in-place
// ---------------------------------------------------------------------------
__global__ void normalize_kernel(float* __restrict__ out) {
    int n = blockIdx.x;
    float* row = out + (size_t)n * OO;
    __shared__ float red[8];

    int t = threadIdx.x;
    float2 v = ((float2*)row)[t];
    float s = v.x * v.x + v.y * v.y;
    #pragma unroll
    for (int o = 16; o; o >>= 1) s += __shfl_xor_sync(0xffffffffu, s, o);
    if ((t & 31) == 0) red[t >> 5] = s;
    __syncthreads();
    if (t == 0) {
        float tot = 0.f;
        #pragma unroll
        for (int w = 0; w < 8; w++) tot += red[w];
        red[0] = tot;
    }
    __syncthreads();
    float inv = 1.f / fmaxf(sqrtf(red[0]), 1e-12f);
    v.x *= inv; v.y *= inv;
    ((float2*)row)[t] = v;
}

// ---------------------------------------------------------------------------
extern "C" void kernel_launch(void* const* d_in, const int* in_sizes, int n_in,
                              void* d_out, int out_size) {
    const float* cls = (const float*)d_in[0];   // (2048, 512)
    const float* pt  = (const float*)d_in[1];   // (2048, 196, 768)
    const float* Wp  = (const float*)d_in[2];   // (512, 768)
    const float* Wf  = (const float*)d_in[3];   // (512, 1024)
    float* out = (float*)d_out;                 // (2048, 512)

    __half *a_p, *f_p, *wp_p, *wf_p;
    cudaGetSymbolAddress((void**)&a_p,  g_A);
    cudaGetSymbolAddress((void**)&f_p,  g_F);
    cudaGetSymbolAddress((void**)&wp_p, g_WpH);
    cudaGetSymbolAddress((void**)&wf_p, g_WfH);

    cudaFuncSetAttribute(gemm_mma<DD / 64, true>,
                         cudaFuncAttributeMaxDynamicSharedMemorySize, SM_TOTAL);
    cudaFuncSetAttribute(gemm_mma<(2 * OO) / 64, false>,
                         cudaFuncAttributeMaxDynamicSharedMemorySize, SM_TOTAL);

    prep_kernel<<<(NWP + NWF + NCLS + 255) / 256, 256>>>(Wp, Wf, cls);
    norm_topk_kernel<<<NB, 256>>>(pt);
    gemm_mma<DD / 64, true><<<dim3(OO / 256, MTOT / 128), 256, SM_TOTAL>>>(
        a_p, wp_p, DD, f_p);
    gemm_mma<(2 * OO) / 64, false><<<dim3(OO / 256, NB / 128), 256, SM_TOTAL>>>(
        f_p, wf_p, 2 * OO, out);
    normalize_kernel<<<NB, 256>>>(out);
}

// round 9
// speedup vs baseline: 1.7316x; 1.0585x over previous
#include <cuda_runtime.h>
#include <cuda_fp16.h>
#include <cstdint>

#define NB 2048   // batch
#define PP 196    // patches
#define DD 768    // patch dim
#define OO 512    // output dim
#define KT 16     // top-k
#define MTOT (NB * KT)   // 32768 gathered rows

// ---------------- device scratch (no allocations allowed) -------------------
__device__ int    g_topk[MTOT];
__device__ __half g_A[MTOT * DD];        // gathered patches, fp16
__device__ __half g_F[NB * 2 * OO];      // fusion input [cls | local], fp16
__device__ __half g_WpH[OO * DD];
__device__ __half g_WfH[OO * 2 * OO];

// ---------------- helpers ----------------------------------------------------
__device__ __forceinline__ uint32_t smem_u32(const void* p) {
    uint32_t a;
    asm("{ .reg .u64 t; cvta.to.shared.u64 t, %1; cvt.u32.u64 %0, t; }" : "=r"(a) : "l"(p));
    return a;
}
#define CP_ASYNC16(dst, src) \
    asm volatile("cp.async.cg.shared.global [%0], [%1], 16;" :: "r"(dst), "l"(src) : "memory")
#define CP_COMMIT() asm volatile("cp.async.commit_group;" ::: "memory")
#define CP_WAIT2()  asm volatile("cp.async.wait_group 2;" ::: "memory")
#define LDMATRIX_X4(r, addr) \
    asm volatile("ldmatrix.sync.aligned.m8n8.x4.shared.b16 {%0,%1,%2,%3}, [%4];" \
        : "=r"((r)[0]), "=r"((r)[1]), "=r"((r)[2]), "=r"((r)[3]) : "r"(addr))
#define MMA16816(d, a, b0, b1) \
    asm volatile("mma.sync.aligned.m16n8k16.row.col.f32.f16.f16.f32 " \
        "{%0,%1,%2,%3}, {%4,%5,%6,%7}, {%8,%9}, {%0,%1,%2,%3};" \
        : "+f"((d)[0]), "+f"((d)[1]), "+f"((d)[2]), "+f"((d)[3]) \
        : "r"((a)[0]), "r"((a)[1]), "r"((a)[2]), "r"((a)[3]), "r"(b0), "r"(b1))

// ---------------------------------------------------------------------------
// Kernel 0: weight conversion fp32 -> fp16 + cls half of fusion input
// ---------------------------------------------------------------------------
#define NWP (OO * DD)            // 393216
#define NWF (OO * 2 * OO)        // 524288
#define NCLS (NB * OO / 2)       // 524288 float2 pairs
__global__ void prep_kernel(const float* __restrict__ Wp, const float* __restrict__ Wf,
                            const float* __restrict__ cls) {
    int i = blockIdx.x * 256 + threadIdx.x;
    if (i < NWP) {
        g_WpH[i] = __float2half_rn(Wp[i]);
    } else if (i < NWP + NWF) {
        int j = i - NWP;
        g_WfH[j] = __float2half_rn(Wf[j]);
    } else if (i < NWP + NWF + NCLS) {
        int j = i - NWP - NWF;              // float2-pair index into cls
        int n = j >> 8, q = j & 255;        // 256 pairs per row
        float2 v = ((const float2*)cls)[j];
        ((__half2*)(g_F + (size_t)n * 2 * OO))[q] = __floats2half2_rn(v.x, v.y);
    }
}

// ---------------------------------------------------------------------------
// Kernel 1: per-patch squared L2 norms + single-warp register top-16 +
// fused gather of the 16 selected rows (L2-hot) into dense fp16 g_A.
// ---------------------------------------------------------------------------
__global__ void norm_topk_kernel(const float* __restrict__ pt) {
    int n = blockIdx.x;
    __shared__ float norms[PP];
    __shared__ int   sel[KT];

    const float* base = pt + (size_t)n * PP * DD;
    int warp = threadIdx.x >> 5, lane = threadIdx.x & 31;

    for (int p = warp; p < PP; p += 8) {
        const float4* row = (const float4*)(base + p * DD);
        float s = 0.f;
        #pragma unroll
        for (int j = 0; j < (DD / 4) / 32; j++) {
            float4 q = row[j * 32 + lane];
            s += q.x * q.x + q.y * q.y + q.z * q.z + q.w * q.w;
        }
        #pragma unroll
        for (int o = 16; o; o >>= 1) s += __shfl_xor_sync(0xffffffffu, s, o);
        if (lane == 0) norms[p] = s;
    }
    __syncthreads();

    if (warp == 0) {
        float v[7];
        #pragma unroll
        for (int j = 0; j < 7; j++) {
            int p = lane + 32 * j;
            v[j] = (p < PP) ? norms[p] : -1e30f;
        }
        #pragma unroll 1
        for (int it = 0; it < KT; it++) {
            float mx = v[0]; int mj = 0;
            #pragma unroll
            for (int j = 1; j < 7; j++) if (v[j] > mx) { mx = v[j]; mj = j; }
            float bmx = mx; int bl = lane;
            #pragma unroll
            for (int o = 16; o; o >>= 1) {
                float om = __shfl_xor_sync(0xffffffffu, bmx, o);
                int   ol = __shfl_xor_sync(0xffffffffu, bl, o);
                if (om > bmx || (om == bmx && ol < bl)) { bmx = om; bl = ol; }
            }
            int wmj = __shfl_sync(0xffffffffu, mj, bl);
            if (lane == bl) v[mj] = -1e30f;
            if (lane == 0) {
                int p = bl + 32 * wmj;
                g_topk[n * KT + it] = p;
                sel[it] = p;
            }
        }
    }
    __syncthreads();

    // gather: 8 warps x 2 slots each, rows still L2-resident
    #pragma unroll
    for (int s = 0; s < 2; s++) {
        int slot = warp + s * 8;
        const float4* src = (const float4*)(base + sel[slot] * DD);
        uint2* dst = (uint2*)(g_A + (size_t)(n * KT + slot) * DD);
        #pragma unroll
        for (int j = 0; j < 6; j++) {
            float4 q = src[j * 32 + lane];
            __half2 h0 = __floats2half2_rn(q.x, q.y);
            __half2 h1 = __floats2half2_rn(q.z, q.w);
            dst[j * 32 + lane] = make_uint2(*(uint32_t*)&h0, *(uint32_t*)&h1);
        }
    }
}

// ---------------------------------------------------------------------------
// Kernel 2/3: fp16 HMMA GEMM, tile-size templated. 8 warps (2m x 4n),
// BK=64, cp.async 4-stage single-sync pipeline, 144B padded rows.
//   C[m,o] = sum_k A[m,k] * B[o,k]
// MAXEPI: max over 16-row groups -> fp16 into g_F[:, 512:]; else fp32 store.
// ---------------------------------------------------------------------------
#define ROWB  144

template<int BM, int BN, int NCH, bool MAXEPI>
__global__ void __launch_bounds__(256, 1) gemm_mma(
    const __half* __restrict__ A, const __half* __restrict__ B,
    int ldk, void* __restrict__ outp)
{
    constexpr int SMA = BM * ROWB;
    constexpr int SMB = BN * ROWB;
    constexpr int STAGE = SMA + SMB;
    constexpr int WTM = BM / 2;          // warp tile m
    constexpr int WTN = BN / 4;          // warp tile n
    constexpr int MF = WTM / 16;         // a-frags (16 rows each)
    constexpr int NBB = WTN / 16;        // b ldmatrix blocks (16 rows each)
    constexpr int NF = WTN / 8;          // n-frags (8 cols each)

    extern __shared__ char smem[];
    uint32_t sb = smem_u32(smem);
    int tid = threadIdx.x, lane = tid & 31, wid = tid >> 5;
    int bn = blockIdx.x, bm = blockIdx.y;
    int warp_m = wid & 1, warp_n = wid >> 1;

    // ---- async loader: chunk c (64 cols) into stage b
    auto issue = [&](int c, int b) {
        int kt = c * 64;
        uint32_t s0 = sb + b * STAGE;
        #pragma unroll
        for (int i = 0; i < BM * 8 / 256; i++) {
            int idx = i * 256 + tid, r = idx >> 3, q = idx & 7;
            CP_ASYNC16(s0 + r * ROWB + q * 16,
                       (const char*)(A + (size_t)(bm * BM + r) * ldk + kt) + q * 16);
        }
        #pragma unroll
        for (int i = 0; i < BN * 8 / 256; i++) {
            int idx = i * 256 + tid, r = idx >> 3, q = idx & 7;
            CP_ASYNC16(s0 + SMA + r * ROWB + q * 16,
                       (const char*)(B + (size_t)(bn * BN + r) * ldk + kt) + q * 16);
        }
        CP_COMMIT();
    };

    float acc[MF][NF][4] = {};

    issue(0, 0);
    issue(1, 1);
    issue(2, 2);

    for (int c = 0; c < NCH; c++) {
        CP_WAIT2();
        __syncthreads();   // chunk c visible; buffer (c+3)&3 free
        if (c + 3 < NCH) issue(c + 3, (c + 3) & 3); else CP_COMMIT();

        uint32_t s0 = sb + (c & 3) * STAGE;
        #pragma unroll
        for (int ks = 0; ks < 4; ks++) {
            uint32_t a[MF][4], b[NBB][4];
            uint32_t arow = warp_m * WTM + (lane & 15);
            uint32_t acol = (ks * 16 + (lane >> 4) * 8) * 2;
            #pragma unroll
            for (int mf = 0; mf < MF; mf++)
                LDMATRIX_X4(a[mf], s0 + (arow + mf * 16) * ROWB + acol);
            uint32_t brow = warp_n * WTN + (lane & 7) + ((lane >> 4) & 1) * 8;
            uint32_t bcol = (ks * 16 + ((lane >> 3) & 1) * 8) * 2;
            #pragma unroll
            for (int nb = 0; nb < NBB; nb++)
                LDMATRIX_X4(b[nb], s0 + SMA + (brow + nb * 16) * ROWB + bcol);
            #pragma unroll
            for (int mf = 0; mf < MF; mf++)
                #pragma unroll
                for (int nf = 0; nf < NF; nf++)
                    MMA16816(acc[mf][nf], a[mf], b[nf >> 1][(nf & 1) * 2], b[nf >> 1][(nf & 1) * 2 + 1]);
        }
    }

    if (MAXEPI) {
        __half* fout = (__half*)outp;
        #pragma unroll
        for (int mf = 0; mf < MF; mf++) {
            int nrow = bm * (BM / 16) + warp_m * MF + mf;    // batch index
            #pragma unroll
            for (int nf = 0; nf < NF; nf++) {
                float m0 = fmaxf(acc[mf][nf][0], acc[mf][nf][2]);
                float m1 = fmaxf(acc[mf][nf][1], acc[mf][nf][3]);
                #pragma unroll
                for (int o = 4; o < 32; o <<= 1) {
                    m0 = fmaxf(m0, __shfl_xor_sync(0xffffffffu, m0, o));
                    m1 = fmaxf(m1, __shfl_xor_sync(0xffffffffu, m1, o));
                }
                if (lane < 4) {
                    int col = OO + bn * BN + warp_n * WTN + nf * 8 + lane * 2;
                    __half2 h = __floats2half2_rn(m0, m1);
                    *(__half2*)&fout[(size_t)nrow * (2 * OO) + col] = h;
                }
            }
        }
    } else {
        float* out = (float*)outp;
        #pragma unroll
        for (int mf = 0; mf < MF; mf++) {
            int r0 = bm * BM + warp_m * WTM + mf * 16 + (lane >> 2);
            #pragma unroll
            for (int nf = 0; nf < NF; nf++) {
                int col = bn * BN + warp_n * WTN + nf * 8 + (lane & 3) * 2;
                *(float2*)&out[(size_t)r0 * OO + col] =
                    make_float2(acc[mf][nf][0], acc[mf][nf][1]);
                *(float2*)&out[(size_t)(r0 + 8) * OO + col] =
                    make_float2(acc[mf][nf][2], acc[mf][nf][3]);
            }
        }
    }
}

// ---------------------------------------------------------------------------
// Kernel 4: row L2 normalize in-place
// ---------------------------------------------------------------------------
__global__ void normalize_kernel(float* __restrict__ out) {
    int n = blockIdx.x;
    float* row = out + (size_t)n * OO;
    __shared__ float red[8];

    int t = threadIdx.x;
    float2 v = ((float2*)row)[t];
    float s = v.x * v.x + v.y * v.y;
    #pragma unroll
    for (int o = 16; o; o >>= 1) s += __shfl_xor_sync(0xffffffffu, s, o);
    if ((t & 31) == 0) red[t >> 5] = s;
    __syncthreads();
    if (t == 0) {
        float tot = 0.f;
        #pragma unroll
        for (int w = 0; w < 8; w++) tot += red[w];
        red[0] = tot;
    }
    __syncthreads();
    float inv = 1.f / fmaxf(sqrtf(red[0]), 1e-12f);
    v.x *= inv; v.y *= inv;
    ((float2*)row)[t] = v;
}

// ---------------------------------------------------------------------------
extern "C" void kernel_launch(void* const* d_in, const int* in_sizes, int n_in,
                              void* d_out, int out_size) {
    const float* cls = (const float*)d_in[0];   // (2048, 512)
    const float* pt  = (const float*)d_in[1];   // (2048, 196, 768)
    const float* Wp  = (const float*)d_in[2];   // (512, 768)
    const float* Wf  = (const float*)d_in[3];   // (512, 1024)
    float* out = (float*)d_out;                 // (2048, 512)

    __half *a_p, *f_p, *wp_p, *wf_p;
    cudaGetSymbolAddress((void**)&a_p,  g_A);
    cudaGetSymbolAddress((void**)&f_p,  g_F);
    cudaGetSymbolAddress((void**)&wp_p, g_WpH);
    cudaGetSymbolAddress((void**)&wf_p, g_WfH);

    // local GEMM: BM=128, BN=256 -> grid (2, 256) = 512 CTAs
    constexpr int SM_LOCAL = 4 * (128 + 256) * ROWB;   // 221184
    // fuse GEMM: BM=64, BN=128 -> grid (4, 32) = 128 CTAs
    constexpr int SM_FUSE  = 4 * (64 + 128) * ROWB;    // 110592

    cudaFuncSetAttribute(gemm_mma<128, 256, DD / 64, true>,
                         cudaFuncAttributeMaxDynamicSharedMemorySize, SM_LOCAL);
    cudaFuncSetAttribute(gemm_mma<64, 128, (2 * OO) / 64, false>,
                         cudaFuncAttributeMaxDynamicSharedMemorySize, SM_FUSE);

    prep_kernel<<<(NWP + NWF + NCLS + 255) / 256, 256>>>(Wp, Wf, cls);
    norm_topk_kernel<<<NB, 256>>>(pt);
    gemm_mma<128, 256, DD / 64, true><<<dim3(OO / 256, MTOT / 128), 256, SM_LOCAL>>>(
        a_p, wp_p, DD, f_p);
    gemm_mma<64, 128, (2 * OO) / 64, false><<<dim3(OO / 128, NB / 64), 256, SM_FUSE>>>(
        f_p, wf_p, 2 * OO, out);
    normalize_kernel<<<NB, 256>>>(out);
}